// round 3
// baseline (speedup 1.0000x reference)
#include <cuda_runtime.h>

#define NN 100000
#define EE 1600000
#define GG 64
#define HID 64
#define EDIM 16
#define OUTD 128

// ---------------- scratch (device globals; no allocation) ----------------
__device__ float d_cnt[NN];
__device__ float d_loop[NN * EDIM];
__device__ float d_xl[NN * HID];
__device__ float d_xr[NN * HID];
__device__ float d_acc[NN * HID];
__device__ float d_den[NN * 4];
__device__ float d_x[NN * HID];
__device__ float d_g[GG * HID];
__device__ float d_gc[GG];

__device__ __forceinline__ void red4(float* p, float a, float b, float c, float d) {
    asm volatile("red.global.add.v4.f32 [%0], {%1,%2,%3,%4};"
                 :: "l"(p), "f"(a), "f"(b), "f"(c), "f"(d) : "memory");
}
__device__ __forceinline__ void red2(float* p, float a, float b) {
    asm volatile("red.global.add.v2.f32 [%0], {%1,%2};"
                 :: "l"(p), "f"(a), "f"(b) : "memory");
}

// ---------------- self-loop mean edge attr ----------------
__global__ void loop_accum_k(const int* __restrict__ ei, const float* __restrict__ ea) {
    int e = blockIdx.x * blockDim.x + threadIdx.x;
    if (e >= EE) return;
    int dst = ei[EE + e];
    const float4* a4 = reinterpret_cast<const float4*>(ea + (size_t)e * EDIM);
    float* o = d_loop + (size_t)dst * EDIM;
#pragma unroll
    for (int i = 0; i < 4; i++) {
        float4 v = a4[i];
        red4(o + 4 * i, v.x, v.y, v.z, v.w);
    }
    atomicAdd(&d_cnt[dst], 1.0f);
}

__global__ void loop_norm_k() {
    int t = blockIdx.x * blockDim.x + threadIdx.x;
    if (t >= NN * EDIM) return;
    float c = d_cnt[t >> 4];
    d_loop[t] = d_loop[t] / fmaxf(c, 1.0f);
}

// ---------------- node projections ----------------
__global__ void node_proj_k(const float* __restrict__ x,
                            const float* __restrict__ Wl, const float* __restrict__ bl,
                            const float* __restrict__ Wr, const float* __restrict__ br) {
    __shared__ float sWl[64 * 64];
    __shared__ float sWr[64 * 64];
    __shared__ float sx[16 * 64];
    for (int i = threadIdx.x; i < 64 * 64; i += blockDim.x) {
        sWl[i] = Wl[i];
        sWr[i] = Wr[i];
    }
    int c  = threadIdx.x & 63;
    int rl = threadIdx.x >> 6;
    float blc = bl[c], brc = br[c];
    for (int base = blockIdx.x * 16; base < NN; base += gridDim.x * 16) {
        __syncthreads();
        for (int i = threadIdx.x; i < 16 * 64; i += 256) {
            int r = base + (i >> 6);
            sx[i] = (r < NN) ? x[(size_t)r * 64 + (i & 63)] : 0.0f;
        }
        __syncthreads();
        float s0 = blc, s1 = blc, s2 = blc, s3 = blc;
        float t0 = brc, t1 = brc, t2 = brc, t3 = brc;
        const float* xrow = sx + rl * 4 * 64;
#pragma unroll
        for (int k = 0; k < 64; k++) {
            float wl = sWl[k * 64 + c];
            float wr = sWr[k * 64 + c];
            float x0 = xrow[0 * 64 + k];
            float x1 = xrow[1 * 64 + k];
            float x2 = xrow[2 * 64 + k];
            float x3 = xrow[3 * 64 + k];
            s0 += x0 * wl; t0 += x0 * wr;
            s1 += x1 * wl; t1 += x1 * wr;
            s2 += x2 * wl; t2 += x2 * wr;
            s3 += x3 * wl; t3 += x3 * wr;
        }
        int r0 = base + rl * 4;
        if (r0 + 0 < NN) { d_xl[(size_t)(r0 + 0) * 64 + c] = s0; d_xr[(size_t)(r0 + 0) * 64 + c] = t0; }
        if (r0 + 1 < NN) { d_xl[(size_t)(r0 + 1) * 64 + c] = s1; d_xr[(size_t)(r0 + 1) * 64 + c] = t1; }
        if (r0 + 2 < NN) { d_xl[(size_t)(r0 + 2) * 64 + c] = s2; d_xr[(size_t)(r0 + 2) * 64 + c] = t2; }
        if (r0 + 3 < NN) { d_xl[(size_t)(r0 + 3) * 64 + c] = s3; d_xr[(size_t)(r0 + 3) * 64 + c] = t3; }
    }
}

// ---------------- fused edge pass ----------------
// One warp per edge; lane l owns channels {2l,2l+1}; head = lane>>3.
// ea row loaded warp-uniform (L1 broadcast) into registers -> no shuffles in eproj.
__global__ void edge_pass_k(const int* __restrict__ ei, const float* __restrict__ ea,
                            const float* __restrict__ We, const float* __restrict__ att) {
    const unsigned F = 0xffffffffu;
    int lane = threadIdx.x & 31;

    float2 w[EDIM];
    const float2* We2 = reinterpret_cast<const float2*>(We);
#pragma unroll
    for (int k = 0; k < EDIM; k++) w[k] = We2[k * 32 + lane];
    float2 at = reinterpret_cast<const float2*>(att)[lane];

    int wid = (blockIdx.x * blockDim.x + threadIdx.x) >> 5;
    int nwarp = (gridDim.x * blockDim.x) >> 5;
    const float2* xl2p = reinterpret_cast<const float2*>(d_xl);
    const float2* xr2p = reinterpret_cast<const float2*>(d_xr);

    for (int e = wid; e < EE + NN; e += nwarp) {
        int src, dst;
        const float4* eap;
        if (e < EE) {
            src = ei[e];
            dst = ei[EE + e];
            eap = reinterpret_cast<const float4*>(ea + (size_t)e * EDIM);
        } else {
            src = dst = e - EE;
            eap = reinterpret_cast<const float4*>(d_loop + (size_t)(e - EE) * EDIM);
        }
        // issue all loads up front (MLP)
        float4 a0 = eap[0], a1 = eap[1], a2 = eap[2], a3 = eap[3];
        float2 xl2 = xl2p[(size_t)src * 32 + lane];
        float2 xr2 = xr2p[(size_t)dst * 32 + lane];

        float av[EDIM];
        av[0]=a0.x; av[1]=a0.y; av[2]=a0.z; av[3]=a0.w;
        av[4]=a1.x; av[5]=a1.y; av[6]=a1.z; av[7]=a1.w;
        av[8]=a2.x; av[9]=a2.y; av[10]=a2.z; av[11]=a2.w;
        av[12]=a3.x; av[13]=a3.y; av[14]=a3.z; av[15]=a3.w;

        float epx = 0.0f, epy = 0.0f;
#pragma unroll
        for (int k = 0; k < EDIM; k++) {
            epx += av[k] * w[k].x;
            epy += av[k] * w[k].y;
        }
        float m0 = xl2.x + xr2.x + epx;
        float m1 = xl2.y + xr2.y + epy;
        m0 = (m0 > 0.0f) ? m0 : 0.2f * m0;
        m1 = (m1 > 0.0f) ? m1 : 0.2f * m1;
        float s = m0 * at.x + m1 * at.y;
        s += __shfl_xor_sync(F, s, 1);
        s += __shfl_xor_sync(F, s, 2);
        s += __shfl_xor_sync(F, s, 4);
        float z = __expf(s);

        red2(d_acc + (size_t)dst * 64 + 2 * lane, z * xl2.x, z * xl2.y);
        if ((lane & 7) == 0)
            atomicAdd(&d_den[(size_t)dst * 4 + (lane >> 3)], z);
    }
}

// ---------------- finalize layer 0: d_x = relu(acc/den + bias), float4 ----------------
__global__ void node_out_k(const float* __restrict__ bias) {
    int t = blockIdx.x * blockDim.x + threadIdx.x;
    if (t >= NN * 16) return;
    int node = t >> 4;
    int part = t & 15;
    float den = d_den[node * 4 + (part >> 2)];
    float inv = 1.0f / den;
    float4 a = reinterpret_cast<const float4*>(d_acc)[t];
    float4 b = reinterpret_cast<const float4*>(bias)[part];
    float4 v;
    v.x = fmaxf(a.x * inv + b.x, 0.0f);
    v.y = fmaxf(a.y * inv + b.y, 0.0f);
    v.z = fmaxf(a.z * inv + b.z, 0.0f);
    v.w = fmaxf(a.w * inv + b.w, 0.0f);
    reinterpret_cast<float4*>(d_x)[t] = v;
}

// ---------------- finalize layer 1 fused with global mean pool ----------------
__global__ void node_out_pool_k(const float* __restrict__ bias, const int* __restrict__ batch) {
    int t = blockIdx.x * blockDim.x + threadIdx.x;
    if (t >= NN * 16) return;
    int node = t >> 4;
    int part = t & 15;
    float den = d_den[node * 4 + (part >> 2)];
    float inv = 1.0f / den;
    float4 a = reinterpret_cast<const float4*>(d_acc)[t];
    float4 b = reinterpret_cast<const float4*>(bias)[part];
    float vx = fmaxf(a.x * inv + b.x, 0.0f);
    float vy = fmaxf(a.y * inv + b.y, 0.0f);
    float vz = fmaxf(a.z * inv + b.z, 0.0f);
    float vw = fmaxf(a.w * inv + b.w, 0.0f);
    int g = batch[node];
    red4(d_g + g * 64 + part * 4, vx, vy, vz, vw);
    if (part == 0) atomicAdd(&d_gc[g], 1.0f);
}

// ---------------- MLP head ----------------
__global__ void mlp_k(const float* __restrict__ W1, const float* __restrict__ b1,
                      const float* __restrict__ W2, const float* __restrict__ b2,
                      float* __restrict__ out) {
    __shared__ float gx[64];
    __shared__ float hh[128];
    int g = blockIdx.x;
    int t = threadIdx.x;
    if (t < 64) gx[t] = d_g[g * 64 + t] / fmaxf(d_gc[g], 1.0f);
    __syncthreads();
    float s = b1[t];
#pragma unroll
    for (int k = 0; k < 64; k++) s += gx[k] * W1[k * 128 + t];
    hh[t] = fmaxf(s, 0.0f);
    __syncthreads();
    float o = b2[t];
#pragma unroll
    for (int k = 0; k < 128; k++) o += hh[k] * W2[k * 128 + t];
    out[g * 128 + t] = o;
}

// ---------------- launch ----------------
extern "C" void kernel_launch(void* const* d_in, const int* in_sizes, int n_in,
                              void* d_out, int out_size) {
    const float* x0     = (const float*)d_in[0];
    const int*   ei     = (const int*)d_in[1];
    const float* ea     = (const float*)d_in[2];
    const int*   batch  = (const int*)d_in[3];
    const float* l0Wl   = (const float*)d_in[4];
    const float* l0bl   = (const float*)d_in[5];
    const float* l0Wr   = (const float*)d_in[6];
    const float* l0br   = (const float*)d_in[7];
    const float* l0We   = (const float*)d_in[8];
    const float* l0att  = (const float*)d_in[9];
    const float* l0bias = (const float*)d_in[10];
    const float* l1Wl   = (const float*)d_in[11];
    const float* l1bl   = (const float*)d_in[12];
    const float* l1Wr   = (const float*)d_in[13];
    const float* l1br   = (const float*)d_in[14];
    const float* l1We   = (const float*)d_in[15];
    const float* l1att  = (const float*)d_in[16];
    const float* l1bias = (const float*)d_in[17];
    const float* W1     = (const float*)d_in[18];
    const float* b1     = (const float*)d_in[19];
    const float* W2     = (const float*)d_in[20];
    const float* b2     = (const float*)d_in[21];
    float* out = (float*)d_out;

    void *pcnt, *ploop, *pacc, *pden, *pg, *pgc, *px;
    cudaGetSymbolAddress(&pcnt, d_cnt);
    cudaGetSymbolAddress(&ploop, d_loop);
    cudaGetSymbolAddress(&pacc, d_acc);
    cudaGetSymbolAddress(&pden, d_den);
    cudaGetSymbolAddress(&pg, d_g);
    cudaGetSymbolAddress(&pgc, d_gc);
    cudaGetSymbolAddress(&px, d_x);

    cudaMemsetAsync(pcnt, 0, NN * sizeof(float));
    cudaMemsetAsync(ploop, 0, NN * EDIM * sizeof(float));
    cudaMemsetAsync(pg, 0, GG * HID * sizeof(float));
    cudaMemsetAsync(pgc, 0, GG * sizeof(float));

    loop_accum_k<<<(EE + 255) / 256, 256>>>(ei, ea);
    loop_norm_k<<<(NN * EDIM + 255) / 256, 256>>>();

    // ---- layer 0 ----
    node_proj_k<<<2048, 256>>>(x0, l0Wl, l0bl, l0Wr, l0br);
    cudaMemsetAsync(pacc, 0, (size_t)NN * HID * sizeof(float));
    cudaMemsetAsync(pden, 0, (size_t)NN * 4 * sizeof(float));
    edge_pass_k<<<2368, 128>>>(ei, ea, l0We, l0att);
    node_out_k<<<(NN * 16 + 255) / 256, 256>>>(l0bias);

    // ---- layer 1 ----
    node_proj_k<<<2048, 256>>>((const float*)px, l1Wl, l1bl, l1Wr, l1br);
    cudaMemsetAsync(pacc, 0, (size_t)NN * HID * sizeof(float));
    cudaMemsetAsync(pden, 0, (size_t)NN * 4 * sizeof(float));
    edge_pass_k<<<2368, 128>>>(ei, ea, l1We, l1att);
    node_out_pool_k<<<(NN * 16 + 255) / 256, 256>>>(l1bias, batch);

    // ---- MLP ----
    mlp_k<<<GG, OUTD>>>(W1, b1, W2, b2, out);
}